// round 8
// baseline (speedup 1.0000x reference)
#include <cuda_runtime.h>

#define NG    64
#define DIM   240
#define NSTAT 16
#define EPS   1e-5f

// Scratch: accumulators + per-(graph,col) affine tables. No device allocation.
__device__ float g_sums[NG * NSTAT];
__device__ float g_A[NG * DIM];
__device__ float g_B[NG * DIM];

__global__ void zero_stats() {
    int t = blockIdx.x * blockDim.x + threadIdx.x;
    if (t < NG * NSTAT) g_sums[t] = 0.f;
}

__device__ __forceinline__ float warp_sum(float v) {
#pragma unroll
    for (int o = 16; o; o >>= 1) v += __shfl_down_sync(0xffffffffu, v, o);
    return v;
}

// One warp per contiguous chunk of rows. batch is sorted, so each warp
// accumulates per-graph stats in registers and flushes (warp-reduce +
// atomics) only on graph transitions (~1-3 flushes per warp total).
//
// Column -> lane mapping (stride 32 across lanes, fully coalesced):
//   seg0 (l=0, cols   0.. 63): lane, lane+32            -> sum, sumsq
//   seg1 (l=1, cols  64..159): 64+32k+lane, k=0..2      -> d=(lane+2k)%3
//   seg2 (l=2, cols 160..239): 160+32k+lane, k=0..2(<16)-> d=(lane+2k)%5
__global__ void __launch_bounds__(256) stats_kernel(const float* __restrict__ x,
                                                    const int* __restrict__ batch,
                                                    int n) {
    const int lane = threadIdx.x & 31;
    const int wid  = (blockIdx.x * blockDim.x + threadIdx.x) >> 5;
    const int nw   = (gridDim.x * blockDim.x) >> 5;
    const int rpw  = (n + nw - 1) / nw;
    int r = wid * rpw;
    const int r1 = min(r + rpw, n);

    const int l3  = lane % 3;
    const int l5a = lane % 5;        // d of a20
    const int l5b = (lane + 2) % 5;  // d of a21
    const int l5c = (lane + 4) % 5;  // d of a22 (only lane<16)
    const bool half = (lane < 16);

    if (r >= r1) return;
    int g = __ldg(batch + r);

    while (r < r1) {
        float s0 = 0.f, sq0 = 0.f;
        float a10 = 0.f, a11 = 0.f, a12 = 0.f;
        float a20 = 0.f, a21 = 0.f, a22 = 0.f;
        float cnt = 0.f;
        int gnext = g;

        for (; r < r1; r++) {
            gnext = __ldg(batch + r);
            if (gnext != g) break;
            const float* row = x + (size_t)r * DIM;
            float v0 = row[lane];
            float v1 = row[lane + 32];
            s0 += v0; sq0 = fmaf(v0, v0, sq0);
            s0 += v1; sq0 = fmaf(v1, v1, sq0);
            a10 += row[ 64 + lane];
            a11 += row[ 96 + lane];
            a12 += row[128 + lane];
            a20 += row[160 + lane];
            a21 += row[192 + lane];
            if (half) a22 += row[224 + lane];
            cnt += 1.f;
        }

        // seg1: each lane holds exactly one accumulator per d-residue.
        float b10 = (l3 == 0) ? a10 : (l3 == 1) ? a11 : a12;
        float b11 = (l3 == 0) ? a12 : (l3 == 1) ? a10 : a11;
        float b12 = (l3 == 0) ? a11 : (l3 == 1) ? a12 : a10;

        // seg2: sparse scatter of 2-3 accumulators into 5 residues.
        float b20 = (l5a == 0 ? a20 : 0.f) + (l5b == 0 ? a21 : 0.f) + ((half && l5c == 0) ? a22 : 0.f);
        float b21 = (l5a == 1 ? a20 : 0.f) + (l5b == 1 ? a21 : 0.f) + ((half && l5c == 1) ? a22 : 0.f);
        float b22 = (l5a == 2 ? a20 : 0.f) + (l5b == 2 ? a21 : 0.f) + ((half && l5c == 2) ? a22 : 0.f);
        float b23 = (l5a == 3 ? a20 : 0.f) + (l5b == 3 ? a21 : 0.f) + ((half && l5c == 3) ? a22 : 0.f);
        float b24 = (l5a == 4 ? a20 : 0.f) + (l5b == 4 ? a21 : 0.f) + ((half && l5c == 4) ? a22 : 0.f);

        s0  = warp_sum(s0);  sq0 = warp_sum(sq0);
        b10 = warp_sum(b10); b11 = warp_sum(b11); b12 = warp_sum(b12);
        b20 = warp_sum(b20); b21 = warp_sum(b21); b22 = warp_sum(b22);
        b23 = warp_sum(b23); b24 = warp_sum(b24);

        if (lane == 0) {
            float* s = g_sums + g * NSTAT;
            atomicAdd(s + 0, s0);
            atomicAdd(s + 1, sq0);
            atomicAdd(s + 2, b10);
            atomicAdd(s + 3, b11);
            atomicAdd(s + 4, b12);
            atomicAdd(s + 5, b20);
            atomicAdd(s + 6, b21);
            atomicAdd(s + 7, b22);
            atomicAdd(s + 8, b23);
            atomicAdd(s + 9, b24);
            atomicAdd(s + 10, cnt);
        }
        g = gnext;
    }
}

// Build per-(graph, col) affine params:  y = x*a + b
__global__ void finalize_kernel(const float* __restrict__ weight,
                                const float* __restrict__ bias) {
    int g = blockIdx.x;
    int c = threadIdx.x;
    if (c >= DIM) return;
    const float* s = g_sums + g * NSTAT;
    float cnt = fmaxf(s[10], 1.f);
    float a, b;
    if (c < 64) {
        float invn = 1.f / (cnt * 64.f);
        float mean = s[0] * invn;
        float var  = fmaxf(fmaf(-mean, mean, s[1] * invn), 0.f);
        float inv  = 1.f / (sqrtf(var) + EPS);
        float w = weight[c];
        a = w * inv;
        b = bias[c] - mean * a;
    } else if (c < 160) {
        int cc = c - 64;
        int d = cc % 3, m = cc / 3;
        float mean = s[2 + d] / (cnt * 32.f);
        float w = weight[64 + m];
        a = w;
        b = -mean * w;
    } else {
        int cc = c - 160;
        int d = cc % 5, m = cc / 5;
        float mean = s[5 + d] / (cnt * 16.f);
        float w = weight[96 + m];
        a = w;
        b = -mean * w;
    }
    g_A[g * DIM + c] = a;
    g_B[g * DIM + c] = b;
}

// Streaming pass: y4 = fma(x4, a4[g], b4[g]). a/b tables (122 KB) and batch
// are cache-resident; HBM traffic = 16B read + 16B write per float4.
__global__ void __launch_bounds__(256) apply_kernel(const float4* __restrict__ x4,
                                                    const int* __restrict__ batch,
                                                    float4* __restrict__ out4,
                                                    int n4) {
    int stride = gridDim.x * blockDim.x;
    for (int i = blockIdx.x * blockDim.x + threadIdx.x; i < n4; i += stride) {
        unsigned u   = (unsigned)i;
        unsigned row = u / 60u;             // DIM/4 = 60 float4 per row
        unsigned c4  = u - row * 60u;
        unsigned off = (unsigned)__ldg(batch + row) * DIM + c4 * 4u;
        const float4 a = __ldg(reinterpret_cast<const float4*>(g_A + off));
        const float4 b = __ldg(reinterpret_cast<const float4*>(g_B + off));
        float4 v = x4[i];
        v.x = fmaf(v.x, a.x, b.x);
        v.y = fmaf(v.y, a.y, b.y);
        v.z = fmaf(v.z, a.z, b.z);
        v.w = fmaf(v.w, a.w, b.w);
        out4[i] = v;
    }
}

extern "C" void kernel_launch(void* const* d_in, const int* in_sizes, int n_in,
                              void* d_out, int out_size) {
    const float* x      = (const float*)d_in[0];
    const int*   batch  = (const int*)d_in[1];
    const float* weight = (const float*)d_in[2];
    const float* bias   = (const float*)d_in[3];
    (void)n_in; (void)out_size;

    int n  = in_sizes[1];          // number of nodes (batch length)
    int n4 = n * (DIM / 4);

    zero_stats<<<1, NG * NSTAT>>>();
    stats_kernel<<<592, 256>>>(x, batch, n);      // 4 blocks/SM, 4736 warps
    finalize_kernel<<<NG, DIM>>>(weight, bias);
    apply_kernel<<<1184, 256>>>((const float4*)x, batch, (float4*)d_out, n4);
}

// round 9
// speedup vs baseline: 1.0037x; 1.0037x over previous
#include <cuda_runtime.h>

#define NG    64
#define DIM   240
#define NSTAT 16
#define EPS   1e-5f

// Scratch: accumulators + per-(graph,col) affine tables. No device allocation.
// g_sums is zero at module load; finalize_kernel re-zeroes it after consuming,
// so every graph replay starts from zeros without a dedicated zeroing launch.
__device__ float g_sums[NG * NSTAT];
__device__ float g_A[NG * DIM];
__device__ float g_B[NG * DIM];

__device__ __forceinline__ float warp_sum(float v) {
#pragma unroll
    for (int o = 16; o; o >>= 1) v += __shfl_down_sync(0xffffffffu, v, o);
    return v;
}

// One warp per contiguous chunk of rows. batch is sorted, so each warp
// accumulates per-graph stats in registers and flushes (warp-reduce +
// atomics) only on graph transitions. Rows are processed two at a time
// (16 independent LDGs in flight) when both belong to the current graph.
//
// Column -> lane mapping (stride 32 across lanes, fully coalesced):
//   seg0 (l=0, cols   0.. 63): lane, lane+32            -> sum, sumsq
//   seg1 (l=1, cols  64..159): 64+32k+lane, k=0..2      -> d=(lane+2k)%3
//   seg2 (l=2, cols 160..239): 160+32k+lane, k=0..2(<16)-> d=(lane+2k)%5
__global__ void __launch_bounds__(256) stats_kernel(const float* __restrict__ x,
                                                    const int* __restrict__ batch,
                                                    int n) {
    const int lane = threadIdx.x & 31;
    const int wid  = (blockIdx.x * blockDim.x + threadIdx.x) >> 5;
    const int nw   = (gridDim.x * blockDim.x) >> 5;
    const int rpw  = (n + nw - 1) / nw;
    int r = wid * rpw;
    const int r1 = min(r + rpw, n);

    const int l3  = lane % 3;
    const int l5a = lane % 5;        // d of a20
    const int l5b = (lane + 2) % 5;  // d of a21
    const int l5c = (lane + 4) % 5;  // d of a22 (only lane<16)
    const bool half = (lane < 16);

    if (r >= r1) return;

    while (r < r1) {
        const int g = __ldg(batch + r);   // first row of this run
        float s0 = 0.f, sq0 = 0.f;
        float a10 = 0.f, a11 = 0.f, a12 = 0.f;
        float a20 = 0.f, a21 = 0.f, a22 = 0.f;
        float cnt = 0.f;

        while (r < r1) {
            if (__ldg(batch + r) != g) break;
            const float* rowA = x + (size_t)r * DIM;
            if (r + 1 < r1 && __ldg(batch + r + 1) == g) {
                // two rows of graph g: 16 independent loads
                const float* rowB = rowA + DIM;
                float u0 = rowA[lane],       w0 = rowB[lane];
                float u1 = rowA[lane + 32],  w1 = rowB[lane + 32];
                float u2 = rowA[ 64 + lane], w2 = rowB[ 64 + lane];
                float u3 = rowA[ 96 + lane], w3 = rowB[ 96 + lane];
                float u4 = rowA[128 + lane], w4 = rowB[128 + lane];
                float u5 = rowA[160 + lane], w5 = rowB[160 + lane];
                float u6 = rowA[192 + lane], w6 = rowB[192 + lane];
                float u7 = 0.f, w7 = 0.f;
                if (half) { u7 = rowA[224 + lane]; w7 = rowB[224 + lane]; }
                s0 += u0 + u1 + w0 + w1;
                sq0 = fmaf(u0, u0, sq0); sq0 = fmaf(u1, u1, sq0);
                sq0 = fmaf(w0, w0, sq0); sq0 = fmaf(w1, w1, sq0);
                a10 += u2 + w2;  a11 += u3 + w3;  a12 += u4 + w4;
                a20 += u5 + w5;  a21 += u6 + w6;  a22 += u7 + w7;
                cnt += 2.f;
                r += 2;
            } else {
                float v0 = rowA[lane];
                float v1 = rowA[lane + 32];
                s0 += v0; sq0 = fmaf(v0, v0, sq0);
                s0 += v1; sq0 = fmaf(v1, v1, sq0);
                a10 += rowA[ 64 + lane];
                a11 += rowA[ 96 + lane];
                a12 += rowA[128 + lane];
                a20 += rowA[160 + lane];
                a21 += rowA[192 + lane];
                if (half) a22 += rowA[224 + lane];
                cnt += 1.f;
                r += 1;
            }
        }

        // seg1: each lane holds exactly one accumulator per d-residue.
        float b10 = (l3 == 0) ? a10 : (l3 == 1) ? a11 : a12;
        float b11 = (l3 == 0) ? a12 : (l3 == 1) ? a10 : a11;
        float b12 = (l3 == 0) ? a11 : (l3 == 1) ? a12 : a10;

        // seg2: sparse scatter of 2-3 accumulators into 5 residues.
        float b20 = (l5a == 0 ? a20 : 0.f) + (l5b == 0 ? a21 : 0.f) + ((half && l5c == 0) ? a22 : 0.f);
        float b21 = (l5a == 1 ? a20 : 0.f) + (l5b == 1 ? a21 : 0.f) + ((half && l5c == 1) ? a22 : 0.f);
        float b22 = (l5a == 2 ? a20 : 0.f) + (l5b == 2 ? a21 : 0.f) + ((half && l5c == 2) ? a22 : 0.f);
        float b23 = (l5a == 3 ? a20 : 0.f) + (l5b == 3 ? a21 : 0.f) + ((half && l5c == 3) ? a22 : 0.f);
        float b24 = (l5a == 4 ? a20 : 0.f) + (l5b == 4 ? a21 : 0.f) + ((half && l5c == 4) ? a22 : 0.f);

        s0  = warp_sum(s0);  sq0 = warp_sum(sq0);
        b10 = warp_sum(b10); b11 = warp_sum(b11); b12 = warp_sum(b12);
        b20 = warp_sum(b20); b21 = warp_sum(b21); b22 = warp_sum(b22);
        b23 = warp_sum(b23); b24 = warp_sum(b24);

        if (lane == 0) {
            float* s = g_sums + g * NSTAT;
            atomicAdd(s + 0, s0);
            atomicAdd(s + 1, sq0);
            atomicAdd(s + 2, b10);
            atomicAdd(s + 3, b11);
            atomicAdd(s + 4, b12);
            atomicAdd(s + 5, b20);
            atomicAdd(s + 6, b21);
            atomicAdd(s + 7, b22);
            atomicAdd(s + 8, b23);
            atomicAdd(s + 9, b24);
            atomicAdd(s + 10, cnt);
        }
    }
}

// Build per-(graph, col) affine params (y = x*a + b), then re-zero this
// graph's stats so the next graph replay starts from zeros.
__global__ void finalize_kernel(const float* __restrict__ weight,
                                const float* __restrict__ bias) {
    int g = blockIdx.x;
    int c = threadIdx.x;
    float* sm = g_sums + g * NSTAT;
    if (c < DIM) {
        const float* s = sm;
        float cnt = fmaxf(s[10], 1.f);
        float a, b;
        if (c < 64) {
            float invn = 1.f / (cnt * 64.f);
            float mean = s[0] * invn;
            float var  = fmaxf(fmaf(-mean, mean, s[1] * invn), 0.f);
            float inv  = 1.f / (sqrtf(var) + EPS);
            float w = weight[c];
            a = w * inv;
            b = bias[c] - mean * a;
        } else if (c < 160) {
            int cc = c - 64;
            int d = cc % 3, m = cc / 3;
            float mean = s[2 + d] / (cnt * 32.f);
            float w = weight[64 + m];
            a = w;
            b = -mean * w;
        } else {
            int cc = c - 160;
            int d = cc % 5, m = cc / 5;
            float mean = s[5 + d] / (cnt * 16.f);
            float w = weight[96 + m];
            a = w;
            b = -mean * w;
        }
        g_A[g * DIM + c] = a;
        g_B[g * DIM + c] = b;
    }
    __syncthreads();           // all reads of sm done
    if (c < NSTAT) sm[c] = 0.f;
}

// Streaming pass: y4 = fma(x4, a4[g], b4[g]). a/b tables (122 KB) and batch
// are cache-resident; HBM traffic = 16B read + 16B write per float4.
__global__ void __launch_bounds__(256) apply_kernel(const float4* __restrict__ x4,
                                                    const int* __restrict__ batch,
                                                    float4* __restrict__ out4,
                                                    int n4) {
    int stride = gridDim.x * blockDim.x;
#pragma unroll 4
    for (int i = blockIdx.x * blockDim.x + threadIdx.x; i < n4; i += stride) {
        unsigned u   = (unsigned)i;
        unsigned row = u / 60u;             // DIM/4 = 60 float4 per row
        unsigned c4  = u - row * 60u;
        unsigned off = (unsigned)__ldg(batch + row) * DIM + c4 * 4u;
        const float4 a = __ldg(reinterpret_cast<const float4*>(g_A + off));
        const float4 b = __ldg(reinterpret_cast<const float4*>(g_B + off));
        float4 v = x4[i];
        v.x = fmaf(v.x, a.x, b.x);
        v.y = fmaf(v.y, a.y, b.y);
        v.z = fmaf(v.z, a.z, b.z);
        v.w = fmaf(v.w, a.w, b.w);
        out4[i] = v;
    }
}

extern "C" void kernel_launch(void* const* d_in, const int* in_sizes, int n_in,
                              void* d_out, int out_size) {
    const float* x      = (const float*)d_in[0];
    const int*   batch  = (const int*)d_in[1];
    const float* weight = (const float*)d_in[2];
    const float* bias   = (const float*)d_in[3];
    (void)n_in; (void)out_size;

    int n  = in_sizes[1];          // number of nodes (batch length)
    int n4 = n * (DIM / 4);

    stats_kernel<<<592, 256>>>(x, batch, n);      // 4 blocks/SM, 4736 warps
    finalize_kernel<<<NG, DIM>>>(weight, bias);
    apply_kernel<<<1184, 256>>>((const float4*)x, batch, (float4*)d_out, n4);
}